// round 16
// baseline (speedup 1.0000x reference)
#include <cuda_runtime.h>
#include <cuda_fp16.h>
#include <cstdint>

#define BB 16
#define CC_ 128
#define HH 64
#define WW 64
#define SS 16
#define LL (HH*WW)
#define NSEG 128
#define SEGLEN 32

// ---------------------------------------------------------------------------
// Scratch (no allocations allowed)
__device__ float g_xc[BB*LL*CC_];                         // conv output [b][l][c] fp32
__device__ float g_dt[BB*LL*CC_];                         // dt sigmoid [b][l][c] fp32
__device__ float g_pooled[BB*CC_];
__device__ float g_gate[BB*CC_];
__device__ __align__(16) __half g_xpad[BB*66*66*128];     // [b][r][c][128] fp16
__device__ __align__(16) __half g_wp[9*128*128];          // [tap][co][ci] fp16
__device__ __align__(16) __half g_xcs[BB*LL*128];         // xc fp16 [tok][128]
__device__ __align__(16) __half g_gw[BB*CC_*CC_];         // (gate*dt_w) fp16 [b][o][c]
__device__ float g_C[BB*CC_*NSEG*SS];
__device__ float g_Sdt[BB*CC_*NSEG];
__device__ float g_hin[BB*CC_*NSEG*SS];

// ---------------------------------------------------------------------------
__device__ __forceinline__ uint32_t smem_u32(const void* p) {
    uint32_t a;
    asm("{ .reg .u64 t; cvta.to.shared.u64 t, %1; cvt.u32.u64 %0, t; }" : "=r"(a) : "l"(p));
    return a;
}
__device__ __forceinline__ void cp16(uint32_t dst, const void* src) {
    asm volatile("cp.async.cg.shared.global [%0], [%1], 16;" :: "r"(dst), "l"(src));
}
__device__ __forceinline__ void cp_commit() { asm volatile("cp.async.commit_group;" ::: "memory"); }
template<int N> __device__ __forceinline__ void cp_wait() {
    asm volatile("cp.async.wait_group %0;" :: "n"(N) : "memory");
}
__device__ __forceinline__ void ldsm_x4(uint32_t& r0, uint32_t& r1, uint32_t& r2, uint32_t& r3, uint32_t addr) {
    asm volatile("ldmatrix.sync.aligned.m8n8.x4.shared.b16 {%0,%1,%2,%3}, [%4];"
        : "=r"(r0), "=r"(r1), "=r"(r2), "=r"(r3) : "r"(addr));
}
__device__ __forceinline__ void mma16816(float* c, uint32_t a0, uint32_t a1, uint32_t a2, uint32_t a3,
                                         uint32_t b0, uint32_t b1) {
    asm volatile("mma.sync.aligned.m16n8k16.row.col.f32.f16.f16.f32 "
        "{%0,%1,%2,%3}, {%4,%5,%6,%7}, {%8,%9}, {%0,%1,%2,%3};"
        : "+f"(c[0]), "+f"(c[1]), "+f"(c[2]), "+f"(c[3])
        : "r"(a0), "r"(a1), "r"(a2), "r"(a3), "r"(b0), "r"(b1));
}

// ---------------------------------------------------------------------------
// prep: blockIdx.x < 66*BB -> x padding; else -> weight convert + pooled zero.
__global__ __launch_bounds__(256) void prep_kernel(const float* __restrict__ x,
                                                   const float* __restrict__ cw)
{
    if (blockIdx.x >= 66*BB) {
        int base = (blockIdx.x - 66*BB) * 256 + threadIdx.x;
        if (base < BB*CC_) g_pooled[base] = 0.f;
        if (base < 9*128*128) {
            int t  = base >> 14;
            int co = (base >> 7) & 127;
            int ci = base & 127;
            g_wp[base] = __float2half(cw[(co*CC_ + ci)*9 + t]);
        }
        return;
    }
    const int pr = blockIdx.x % 66;
    const int b  = blockIdx.x / 66;
    const int tid = threadIdx.x;
    uint32_t* outw = reinterpret_cast<uint32_t*>(g_xpad) + ((b*66 + pr)*66) * 64;

    if (pr == 0 || pr == 65) {
        for (int i = tid; i < 66*64; i += 256) outw[i] = 0u;
        return;
    }
    const int hr = pr - 1;
    __shared__ float tile[128*64];
    for (int i = tid; i < 128*64; i += 256) {
        int c = i >> 6, w = i & 63;
        tile[i] = x[((b*CC_ + c)*HH + hr)*WW + w];
    }
    __syncthreads();
    for (int i = tid; i < 66*64; i += 256) {
        int pc = i >> 6, j = i & 63;
        uint32_t v = 0u;
        if (pc >= 1 && pc <= 64) {
            int w = pc - 1;
            int c0 = j*2;
            __half h0 = __float2half(tile[c0*64 + w]);
            __half h1 = __float2half(tile[(c0+1)*64 + w]);
            v = (uint32_t)*reinterpret_cast<uint16_t*>(&h0) |
                ((uint32_t)*reinterpret_cast<uint16_t*>(&h1) << 16);
        }
        outw[i] = v;
    }
}

// ---------------------------------------------------------------------------
// Implicit-GEMM conv, pure fp16 (HMMA). CTA: M=128 x N=128, 8 warps (4m x 2n).
// 18 stages of K=64, single product per stage, double-buffered.
#define ROWSTRIDE 144
#define AST 18432
#define BUFB 36864
#define NSTG 18

__global__ __launch_bounds__(256, 2) void conv_mma_kernel(const float* __restrict__ cbias)
{
    extern __shared__ char dyn[];
    const uint32_t sb = smem_u32(dyn);
    __shared__ float spool[128];

    const int tid  = threadIdx.x;
    const int wid  = tid >> 5;
    const int lane = tid & 31;
    const int mw   = wid & 3;
    const int nw   = wid >> 2;
    const int b    = blockIdx.x >> 5;
    const int tile = blockIdx.x & 31;
    const int R    = tile * 2;

    float acc[2][8][4];
#pragma unroll
    for (int m = 0; m < 2; m++)
#pragma unroll
        for (int n = 0; n < 8; n++)
#pragma unroll
            for (int j = 0; j < 4; j++) acc[m][n][j] = 0.f;

    const int r0 = tid >> 3;
    const int k8 = tid & 7;
    const long a0 = (long)r0*128 + k8*8;
    const long b0 = (long)r0*128 + k8*8;
    const uint32_t d0 = r0*ROWSTRIDE + k8*16;
    const __half* xbase = g_xpad + (long)(b*66 + R)*66*128;
    const __half* wp = g_wp;

    auto issue_loads = [&](int s, uint32_t bufoff) {
        const int t_ = s >> 1;
        const int ch = (s & 1) << 6;
        const int kh = (t_ * 11) >> 5;
        const int kw = t_ - kh*3;
        const long aoff = (long)((kh*66 + kw) << 7) + ch;
        const long boff = ((long)t_ << 14) + ch;
        const uint32_t dbase = sb + bufoff + d0;
#pragma unroll
        for (int i = 0; i < 8; i++) {
            const int q = i & 3;
            if (i < 4) {
                const int cellC = (q & 1)*32 + (q >> 1)*66;
                cp16(dbase + q*32*ROWSTRIDE,
                     xbase + aoff + a0 + (long)cellC*128);
            } else {
                cp16(dbase + AST + q*32*ROWSTRIDE,
                     wp + boff + b0 + q*4096);
            }
        }
    };

    issue_loads(0, 0);
    cp_commit();

    const uint32_t lrow  = (lane & 15);
    const uint32_t lhalf = (lane >> 4) * 16;

    int buf = 0;
    for (int s = 0; s < NSTG; s++) {
        cp_wait<0>();
        __syncthreads();
        if (s + 1 < NSTG) {
            issue_loads(s + 1, (buf ^ 1) * BUFB);
            cp_commit();
        }

        const uint32_t ab = sb + buf*BUFB;
        const uint32_t a0_ = ab + (mw*32 + lrow)*ROWSTRIDE + lhalf;
        const uint32_t a1_ = a0_ + 16*ROWSTRIDE;
        const uint32_t bbase = ab + AST + (nw*64 + lrow)*ROWSTRIDE + lhalf;

#pragma unroll
        for (int ks = 0; ks < 4; ks++) {
            uint32_t bf[8][2];
#pragma unroll
            for (int q = 0; q < 4; q++) {
                uint32_t r0_, r1_, r2_, r3_;
                ldsm_x4(r0_, r1_, r2_, r3_, bbase + q*16*ROWSTRIDE + ks*32);
                bf[q*2][0] = r0_;   bf[q*2][1] = r2_;
                bf[q*2+1][0] = r1_; bf[q*2+1][1] = r3_;
            }
            uint32_t af[2][4];
            ldsm_x4(af[0][0], af[0][1], af[0][2], af[0][3], a0_ + ks*32);
            ldsm_x4(af[1][0], af[1][1], af[1][2], af[1][3], a1_ + ks*32);
#pragma unroll
            for (int m = 0; m < 2; m++)
#pragma unroll
                for (int n = 0; n < 8; n++)
                    mma16816(acc[m][n], af[m][0], af[m][1], af[m][2], af[m][3],
                             bf[n][0], bf[n][1]);
        }
        buf ^= 1;
    }

    __syncthreads();
    if (tid < 128) spool[tid] = 0.f;
    __syncthreads();

    const int qrow = lane >> 2;
    const int qcol = (lane & 3) * 2;
    const long tokbase = (long)(b << 12) + tile*128 + mw*32;
#pragma unroll
    for (int n = 0; n < 8; n++) {
        const int co = nw*64 + n*8 + qcol;
        const float b0f = cbias[co], b1f = cbias[co + 1];
        float ps0 = 0.f, ps1 = 0.f;
#pragma unroll
        for (int m = 0; m < 2; m++) {
#pragma unroll
            for (int h = 0; h < 2; h++) {
                long t0 = tokbase + m*16 + qrow + h*8;
                float v0 = acc[m][n][h*2]   + b0f;
                float v1 = acc[m][n][h*2+1] + b1f;
                ps0 += v0; ps1 += v1;
                *reinterpret_cast<float2*>(g_xc + t0*CC_ + co) = make_float2(v0, v1);
                *reinterpret_cast<__half2*>(g_xcs + (t0 << 7) + co) =
                    __floats2half2_rn(v0, v1);
            }
        }
        atomicAdd(&spool[co], ps0);
        atomicAdd(&spool[co + 1], ps1);
    }
    __syncthreads();
    if (tid < 128) atomicAdd(&g_pooled[b*CC_ + tid], spool[tid]);
}

// ---------------------------------------------------------------------------
// gate: 512 threads = 128 outputs x 4 K-quarters; also emits (g*dt_w) fp16.
__global__ __launch_bounds__(512) void gate_kernel(
    const float* __restrict__ g1w, const float* __restrict__ g1b,
    const float* __restrict__ g2w, const float* __restrict__ g2b,
    const float* __restrict__ dtw)
{
    const int b = blockIdx.x;
    const int tid = threadIdx.x;
    const int o = tid & 127;
    const int h = tid >> 7;          // K-quarter (0..3)
    __shared__ float sp[CC_], st[CC_], part[512], sgate[CC_];

    if (tid < 128) sp[tid] = g_pooled[b*CC_ + tid] * (1.f/(float)LL);
    __syncthreads();

    {
        const float4* wv = reinterpret_cast<const float4*>(g1w + o*CC_ + h*32);
        const float4* xv = reinterpret_cast<const float4*>(sp + h*32);
        float a0 = 0.f, a1 = 0.f;
#pragma unroll
        for (int i = 0; i < 8; i += 2) {
            float4 w0 = wv[i],   x0 = xv[i];
            float4 w1 = wv[i+1], x1 = xv[i+1];
            a0 = fmaf(w0.x,x0.x, fmaf(w0.y,x0.y, fmaf(w0.z,x0.z, fmaf(w0.w,x0.w, a0))));
            a1 = fmaf(w1.x,x1.x, fmaf(w1.y,x1.y, fmaf(w1.z,x1.z, fmaf(w1.w,x1.w, a1))));
        }
        part[tid] = a0 + a1;
    }
    __syncthreads();
    if (tid < 128)
        st[tid] = fmaxf(part[tid] + part[tid+128] + part[tid+256] + part[tid+384]
                        + g1b[tid], 0.f);
    __syncthreads();

    {
        const float4* wv = reinterpret_cast<const float4*>(g2w + o*CC_ + h*32);
        const float4* xv = reinterpret_cast<const float4*>(st + h*32);
        float a0 = 0.f, a1 = 0.f;
#pragma unroll
        for (int i = 0; i < 8; i += 2) {
            float4 w0 = wv[i],   x0 = xv[i];
            float4 w1 = wv[i+1], x1 = xv[i+1];
            a0 = fmaf(w0.x,x0.x, fmaf(w0.y,x0.y, fmaf(w0.z,x0.z, fmaf(w0.w,x0.w, a0))));
            a1 = fmaf(w1.x,x1.x, fmaf(w1.y,x1.y, fmaf(w1.z,x1.z, fmaf(w1.w,x1.w, a1))));
        }
        part[tid] = a0 + a1;
    }
    __syncthreads();
    if (tid < 128) {
        float z = part[tid] + part[tid+128] + part[tid+256] + part[tid+384] + g2b[tid];
        float g = 1.f / (1.f + __expf(-z));
        sgate[tid] = g;
        g_gate[b*CC_ + tid] = g;
    }
    __syncthreads();

    // emit (g * dt_w) fp16 for this batch: 16384 elements, 32 per thread
    __half* gw = g_gw + (long)b*CC_*CC_;
#pragma unroll
    for (int i = 0; i < 16; i++) {
        int idx = tid + i*512;          // [o][c pair]
        int oo = idx >> 6, cp = (idx & 63) * 2;
        float w0 = dtw[oo*CC_ + cp]     * sgate[cp];
        float w1 = dtw[oo*CC_ + cp + 1] * sgate[cp + 1];
        *reinterpret_cast<__half2*>(gw + oo*CC_ + cp) = __floats2half2_rn(w0, w1);
    }
}

// ---------------------------------------------------------------------------
// dt = sigmoid( xc @ (g*W)^T + b ) via HMMA fp16, single product.
// A and B both via cp.async (B from precomputed g_gw fp16).
#define RS2 272
#define DOFF_A 0
#define DOFF_B 34816

__global__ __launch_bounds__(256, 2) void dt_mma_kernel(const float* __restrict__ dtb)
{
    extern __shared__ char dyn2[];
    const uint32_t sb = smem_u32(dyn2);
    const int tid  = threadIdx.x;
    const int wid  = tid >> 5;
    const int lane = tid & 31;
    const int mw   = wid & 3;
    const int nw   = wid >> 2;
    const int m0   = blockIdx.x * 128;
    const int b    = m0 >> 12;

    const __half* gw = g_gw + (long)b*CC_*CC_;
#pragma unroll
    for (int i = 0; i < 16; i++) {
        int idx = tid + i*256;
        if (idx < 2048) {       // A: 128 tokens x 16 chunks
            int tk = idx >> 4, k8 = idx & 15;
            cp16(sb + DOFF_A + tk*RS2 + k8*16, g_xcs + ((long)(m0 + tk) << 7) + (k8 << 3));
        } else {                // B: 128 o x 16 chunks
            int j = idx - 2048;
            int o = j >> 4, k8 = j & 15;
            cp16(sb + DOFF_B + o*RS2 + k8*16, gw + o*CC_ + (k8 << 3));
        }
    }
    cp_commit();
    cp_wait<0>();
    __syncthreads();

    float acc[2][8][4];
#pragma unroll
    for (int m = 0; m < 2; m++)
#pragma unroll
        for (int n = 0; n < 8; n++)
#pragma unroll
            for (int j = 0; j < 4; j++) acc[m][n][j] = 0.f;

    const uint32_t lrow  = (lane & 15);
    const uint32_t lhalf = (lane >> 4) * 16;

    {
        const uint32_t a0 = sb + DOFF_A + (mw*32 + lrow)*RS2 + lhalf;
        const uint32_t a1 = a0 + 16*RS2;
        const uint32_t bbase = sb + DOFF_B + (nw*64 + lrow)*RS2 + lhalf;
#pragma unroll
        for (int ks = 0; ks < 8; ks++) {
            uint32_t af[2][4];
            ldsm_x4(af[0][0], af[0][1], af[0][2], af[0][3], a0 + ks*32);
            ldsm_x4(af[1][0], af[1][1], af[1][2], af[1][3], a1 + ks*32);
            uint32_t bf[8][2];
#pragma unroll
            for (int q = 0; q < 4; q++) {
                uint32_t r0, r1, r2, r3;
                ldsm_x4(r0, r1, r2, r3, bbase + q*16*RS2 + ks*32);
                bf[q*2][0] = r0;   bf[q*2][1] = r2;
                bf[q*2+1][0] = r1; bf[q*2+1][1] = r3;
            }
#pragma unroll
            for (int m = 0; m < 2; m++)
#pragma unroll
                for (int n = 0; n < 8; n++)
                    mma16816(acc[m][n], af[m][0], af[m][1], af[m][2], af[m][3],
                             bf[n][0], bf[n][1]);
        }
    }

    const int qrow = lane >> 2;
    const int qcol = (lane & 3) * 2;
    const long tokbase = (long)m0 + mw*32;
#pragma unroll
    for (int n = 0; n < 8; n++) {
        const int co = nw*64 + n*8 + qcol;
        const float b0 = dtb[co], b1 = dtb[co + 1];
#pragma unroll
        for (int m = 0; m < 2; m++) {
#pragma unroll
            for (int h = 0; h < 2; h++) {
                long t0 = tokbase + m*16 + qrow + h*8;
                float z0 = acc[m][n][h*2]   + b0;
                float z1 = acc[m][n][h*2+1] + b1;
                float2 v = make_float2(1.f/(1.f + __expf(-z0)), 1.f/(1.f + __expf(-z1)));
                *reinterpret_cast<float2*>(g_dt + t0*CC_ + co) = v;
            }
        }
    }
}

// ---------------------------------------------------------------------------
// SSM parallel scan, pass 1: per (b,c,seg) local scan from h=0. SEGLEN=32.
// 8-token register load batching for MLP.
__global__ __launch_bounds__(128) void scan_p1_kernel(const float* __restrict__ Araw)
{
    const int b   = blockIdx.x >> 7;
    const int seg = blockIdx.x & 127;
    const int c   = threadIdx.x;

    const float gc = g_gate[b*CC_ + c];
    float An2[SS], h[SS];
#pragma unroll
    for (int s = 0; s < SS; s++) {
        An2[s] = -__expf(Araw[c*SS + s]) * 1.4426950408889634f;
        h[s] = 0.f;
    }

    const float* xcp = g_xc + ((long)(b*LL) + seg*SEGLEN)*CC_ + c;
    const float* dtp = g_dt + ((long)(b*LL) + seg*SEGLEN)*CC_ + c;
    float sdt = 0.f;

    for (int t0 = 0; t0 < SEGLEN; t0 += 8) {
        float xv[8], dv[8];
#pragma unroll
        for (int j = 0; j < 8; j++) {
            xv[j] = xcp[(t0+j)*CC_];
            dv[j] = dtp[(t0+j)*CC_];
        }
#pragma unroll
        for (int j = 0; j < 8; j++) {
            float x = xv[j] * gc;
            sdt += dv[j];
#pragma unroll
            for (int s = 0; s < SS; s++)
                h[s] = fmaf(h[s], exp2f(An2[s]*dv[j]), x);
        }
    }
    const long pair = (long)b*CC_ + c;
    float* Cp = g_C + (pair*NSEG + seg)*SS;
#pragma unroll
    for (int s = 0; s < SS; s++) Cp[s] = h[s];
    g_Sdt[pair*NSEG + seg] = sdt;
}

// pass 2: per (b,c) serial scan over NSEG segment summaries.
__global__ __launch_bounds__(256) void scan_fix_kernel(const float* __restrict__ Araw)
{
    const int pair = blockIdx.x*16 + (threadIdx.x >> 4);
    const int s    = threadIdx.x & 15;
    const int c    = pair & 127;
    const float An2 = -__expf(Araw[c*SS + s]) * 1.4426950408889634f;

    float h = 0.f;
    const float* Cp = g_C + (long)pair*NSEG*SS;
    const float* Sp = g_Sdt + (long)pair*NSEG;
    float* Hp = g_hin + (long)pair*NSEG*SS;
#pragma unroll 4
    for (int k = 0; k < NSEG; k++) {
        Hp[k*SS + s] = h;
        h = fmaf(h, exp2f(An2 * Sp[k]), Cp[k*SS + s]);
    }
}

// pass 3: rerun each segment from correct h_in, produce y, write NCHW + identity.
__global__ __launch_bounds__(128) void scan_p3_kernel(
    const float* __restrict__ x0,
    const float* __restrict__ Araw,
    const float* __restrict__ Draw,
    float* __restrict__ out)
{
    const int b   = blockIdx.x >> 7;
    const int seg = blockIdx.x & 127;
    const int c   = threadIdx.x;
    const int lane = c & 31;
    const int wrp  = c >> 5;

    __shared__ float ybuf[32][129];

    const float gc = g_gate[b*CC_ + c];
    const float Dp = __expf(Draw[c]);
    float An[SS], An2[SS], h[SS];
    const long pair = (long)b*CC_ + c;
    const float* Hp = g_hin + (pair*NSEG + seg)*SS;
#pragma unroll
    for (int s = 0; s < SS; s++) {
        An[s]  = -__expf(Araw[c*SS + s]);
        An2[s] = An[s] * 1.4426950408889634f;
        h[s]   = Hp[s];
    }

    const float* xcp = g_xc + ((long)(b*LL) + seg*SEGLEN)*CC_ + c;
    const float* dtp = g_dt + ((long)(b*LL) + seg*SEGLEN)*CC_ + c;
    const long l0 = (long)seg*SEGLEN;

    for (int tb = 0; tb < 32; tb += 8) {
        float xv[8], dv[8];
#pragma unroll
        for (int j = 0; j < 8; j++) {
            int tt = tb + j;
            xv[j] = xcp[tt*CC_];
            dv[j] = dtp[tt*CC_];
        }
#pragma unroll
        for (int j = 0; j < 8; j++) {
            float x = xv[j] * gc;
            float y = Dp * x;
#pragma unroll
            for (int s = 0; s < SS; s++) {
                h[s] = fmaf(h[s], exp2f(An2[s]*dv[j]), x);
                y = fmaf(h[s], An[s], y);
            }
            ybuf[tb + j][c] = y;
        }
    }
    __syncthreads();
#pragma unroll 4
    for (int cc = 0; cc < 32; cc++) {
        int co = wrp*32 + cc;
        long gidx = ((long)(b*CC_ + co) << 12) + l0 + lane;
        out[gidx] = ybuf[lane][co] + x0[gidx];
    }
}

// ---------------------------------------------------------------------------
extern "C" void kernel_launch(void* const* d_in, const int* in_sizes, int n_in,
                              void* d_out, int out_size)
{
    const float* x      = (const float*)d_in[0];
    const float* conv_w = (const float*)d_in[1];
    const float* conv_b = (const float*)d_in[2];
    const float* dt_w   = (const float*)d_in[3];
    const float* dt_b   = (const float*)d_in[4];
    const float* A      = (const float*)d_in[5];
    const float* D      = (const float*)d_in[6];
    const float* g1_w   = (const float*)d_in[7];
    const float* g1_b   = (const float*)d_in[8];
    const float* g2_w   = (const float*)d_in[9];
    const float* g2_b   = (const float*)d_in[10];
    float* out = (float*)d_out;

    const int conv_smem = 2 * BUFB;        // 73728
    const int dt_smem   = 2 * 34816;       // 69632
    cudaFuncSetAttribute(conv_mma_kernel, cudaFuncAttributeMaxDynamicSharedMemorySize, conv_smem);
    cudaFuncSetAttribute(dt_mma_kernel,   cudaFuncAttributeMaxDynamicSharedMemorySize, dt_smem);

    const int prep_blocks = 66*BB + (9*128*128 + 255)/256;
    prep_kernel<<<prep_blocks, 256>>>(x, conv_w);
    conv_mma_kernel<<<BB*32, 256, conv_smem>>>(conv_b);
    gate_kernel<<<BB, 512>>>(g1_w, g1_b, g2_w, g2_b, dt_w);
    dt_mma_kernel<<<(BB*LL)/128, 256, dt_smem>>>(dt_b);
    scan_p1_kernel<<<BB*NSEG, 128>>>(A);
    scan_fix_kernel<<<BB*CC_/16, 256>>>(A);
    scan_p3_kernel<<<BB*NSEG, 128>>>(x, A, D, out);
}

// round 17
// speedup vs baseline: 1.0528x; 1.0528x over previous
#include <cuda_runtime.h>
#include <cuda_fp16.h>
#include <cstdint>

#define BB 16
#define CC_ 128
#define HH 64
#define WW 64
#define SS 16
#define LL (HH*WW)
#define NSEG 64
#define SEGLEN 64

// ---------------------------------------------------------------------------
// Scratch (no allocations allowed)
__device__ float g_xc[BB*LL*CC_];                         // conv output [b][l][c] fp32
__device__ float g_dt[BB*LL*CC_];                         // dt sigmoid [b][l][c] fp32
__device__ float g_pooled[BB*CC_];
__device__ float g_gate[BB*CC_];
__device__ __align__(16) __half g_xpad[BB*66*66*128];     // [b][r][c][128] fp16
__device__ __align__(16) __half g_wp[9*128*128];          // [tap][co][ci] fp16
__device__ __align__(16) __half g_xcs[BB*LL*128];         // xc fp16 [tok][128]
__device__ __align__(16) __half g_gw[BB*CC_*CC_];         // (gate*dt_w) fp16 [b][o][c]
__device__ float g_C[BB*CC_*NSEG*SS];
__device__ float g_Sdt[BB*CC_*NSEG];
__device__ float g_hin[BB*CC_*NSEG*SS];

// ---------------------------------------------------------------------------
__device__ __forceinline__ uint32_t smem_u32(const void* p) {
    uint32_t a;
    asm("{ .reg .u64 t; cvta.to.shared.u64 t, %1; cvt.u32.u64 %0, t; }" : "=r"(a) : "l"(p));
    return a;
}
__device__ __forceinline__ void cp16(uint32_t dst, const void* src) {
    asm volatile("cp.async.cg.shared.global [%0], [%1], 16;" :: "r"(dst), "l"(src));
}
__device__ __forceinline__ void cp_commit() { asm volatile("cp.async.commit_group;" ::: "memory"); }
template<int N> __device__ __forceinline__ void cp_wait() {
    asm volatile("cp.async.wait_group %0;" :: "n"(N) : "memory");
}
__device__ __forceinline__ void ldsm_x4(uint32_t& r0, uint32_t& r1, uint32_t& r2, uint32_t& r3, uint32_t addr) {
    asm volatile("ldmatrix.sync.aligned.m8n8.x4.shared.b16 {%0,%1,%2,%3}, [%4];"
        : "=r"(r0), "=r"(r1), "=r"(r2), "=r"(r3) : "r"(addr));
}
__device__ __forceinline__ void mma16816(float* c, uint32_t a0, uint32_t a1, uint32_t a2, uint32_t a3,
                                         uint32_t b0, uint32_t b1) {
    asm volatile("mma.sync.aligned.m16n8k16.row.col.f32.f16.f16.f32 "
        "{%0,%1,%2,%3}, {%4,%5,%6,%7}, {%8,%9}, {%0,%1,%2,%3};"
        : "+f"(c[0]), "+f"(c[1]), "+f"(c[2]), "+f"(c[3])
        : "r"(a0), "r"(a1), "r"(a2), "r"(a3), "r"(b0), "r"(b1));
}

// ---------------------------------------------------------------------------
// prep: blockIdx.x < 66*BB -> x padding; else -> weight convert + pooled zero.
__global__ __launch_bounds__(256) void prep_kernel(const float* __restrict__ x,
                                                   const float* __restrict__ cw)
{
    if (blockIdx.x >= 66*BB) {
        int base = (blockIdx.x - 66*BB) * 256 + threadIdx.x;
        if (base < BB*CC_) g_pooled[base] = 0.f;
        if (base < 9*128*128) {
            int t  = base >> 14;
            int co = (base >> 7) & 127;
            int ci = base & 127;
            g_wp[base] = __float2half(cw[(co*CC_ + ci)*9 + t]);
        }
        return;
    }
    const int pr = blockIdx.x % 66;
    const int b  = blockIdx.x / 66;
    const int tid = threadIdx.x;
    uint32_t* outw = reinterpret_cast<uint32_t*>(g_xpad) + ((b*66 + pr)*66) * 64;

    if (pr == 0 || pr == 65) {
        for (int i = tid; i < 66*64; i += 256) outw[i] = 0u;
        return;
    }
    const int hr = pr - 1;
    __shared__ float tile[128*64];
    for (int i = tid; i < 128*64; i += 256) {
        int c = i >> 6, w = i & 63;
        tile[i] = x[((b*CC_ + c)*HH + hr)*WW + w];
    }
    __syncthreads();
    for (int i = tid; i < 66*64; i += 256) {
        int pc = i >> 6, j = i & 63;
        uint32_t v = 0u;
        if (pc >= 1 && pc <= 64) {
            int w = pc - 1;
            int c0 = j*2;
            __half h0 = __float2half(tile[c0*64 + w]);
            __half h1 = __float2half(tile[(c0+1)*64 + w]);
            v = (uint32_t)*reinterpret_cast<uint16_t*>(&h0) |
                ((uint32_t)*reinterpret_cast<uint16_t*>(&h1) << 16);
        }
        outw[i] = v;
    }
}

// ---------------------------------------------------------------------------
// Implicit-GEMM conv, pure fp16 (HMMA). CTA: M=128 x N=128, 8 warps (4m x 2n).
// 18 stages of K=64, single product per stage, double-buffered.
#define ROWSTRIDE 144
#define AST 18432
#define BUFB 36864
#define NSTG 18

__global__ __launch_bounds__(256, 2) void conv_mma_kernel(const float* __restrict__ cbias)
{
    extern __shared__ char dyn[];
    const uint32_t sb = smem_u32(dyn);
    __shared__ float spool[128];

    const int tid  = threadIdx.x;
    const int wid  = tid >> 5;
    const int lane = tid & 31;
    const int mw   = wid & 3;
    const int nw   = wid >> 2;
    const int b    = blockIdx.x >> 5;
    const int tile = blockIdx.x & 31;
    const int R    = tile * 2;

    float acc[2][8][4];
#pragma unroll
    for (int m = 0; m < 2; m++)
#pragma unroll
        for (int n = 0; n < 8; n++)
#pragma unroll
            for (int j = 0; j < 4; j++) acc[m][n][j] = 0.f;

    const int r0 = tid >> 3;
    const int k8 = tid & 7;
    const long a0 = (long)r0*128 + k8*8;
    const long b0 = (long)r0*128 + k8*8;
    const uint32_t d0 = r0*ROWSTRIDE + k8*16;
    const __half* xbase = g_xpad + (long)(b*66 + R)*66*128;
    const __half* wp = g_wp;

    auto issue_loads = [&](int s, uint32_t bufoff) {
        const int t_ = s >> 1;
        const int ch = (s & 1) << 6;
        const int kh = (t_ * 11) >> 5;
        const int kw = t_ - kh*3;
        const long aoff = (long)((kh*66 + kw) << 7) + ch;
        const long boff = ((long)t_ << 14) + ch;
        const uint32_t dbase = sb + bufoff + d0;
#pragma unroll
        for (int i = 0; i < 8; i++) {
            const int q = i & 3;
            if (i < 4) {
                const int cellC = (q & 1)*32 + (q >> 1)*66;
                cp16(dbase + q*32*ROWSTRIDE,
                     xbase + aoff + a0 + (long)cellC*128);
            } else {
                cp16(dbase + AST + q*32*ROWSTRIDE,
                     wp + boff + b0 + q*4096);
            }
        }
    };

    issue_loads(0, 0);
    cp_commit();

    const uint32_t lrow  = (lane & 15);
    const uint32_t lhalf = (lane >> 4) * 16;

    int buf = 0;
    for (int s = 0; s < NSTG; s++) {
        cp_wait<0>();
        __syncthreads();
        if (s + 1 < NSTG) {
            issue_loads(s + 1, (buf ^ 1) * BUFB);
            cp_commit();
        }

        const uint32_t ab = sb + buf*BUFB;
        const uint32_t a0_ = ab + (mw*32 + lrow)*ROWSTRIDE + lhalf;
        const uint32_t a1_ = a0_ + 16*ROWSTRIDE;
        const uint32_t bbase = ab + AST + (nw*64 + lrow)*ROWSTRIDE + lhalf;

#pragma unroll
        for (int ks = 0; ks < 4; ks++) {
            uint32_t bf[8][2];
#pragma unroll
            for (int q = 0; q < 4; q++) {
                uint32_t r0_, r1_, r2_, r3_;
                ldsm_x4(r0_, r1_, r2_, r3_, bbase + q*16*ROWSTRIDE + ks*32);
                bf[q*2][0] = r0_;   bf[q*2][1] = r2_;
                bf[q*2+1][0] = r1_; bf[q*2+1][1] = r3_;
            }
            uint32_t af[2][4];
            ldsm_x4(af[0][0], af[0][1], af[0][2], af[0][3], a0_ + ks*32);
            ldsm_x4(af[1][0], af[1][1], af[1][2], af[1][3], a1_ + ks*32);
#pragma unroll
            for (int m = 0; m < 2; m++)
#pragma unroll
                for (int n = 0; n < 8; n++)
                    mma16816(acc[m][n], af[m][0], af[m][1], af[m][2], af[m][3],
                             bf[n][0], bf[n][1]);
        }
        buf ^= 1;
    }

    __syncthreads();
    if (tid < 128) spool[tid] = 0.f;
    __syncthreads();

    const int qrow = lane >> 2;
    const int qcol = (lane & 3) * 2;
    const long tokbase = (long)(b << 12) + tile*128 + mw*32;
#pragma unroll
    for (int n = 0; n < 8; n++) {
        const int co = nw*64 + n*8 + qcol;
        const float b0f = cbias[co], b1f = cbias[co + 1];
        float ps0 = 0.f, ps1 = 0.f;
#pragma unroll
        for (int m = 0; m < 2; m++) {
#pragma unroll
            for (int h = 0; h < 2; h++) {
                long t0 = tokbase + m*16 + qrow + h*8;
                float v0 = acc[m][n][h*2]   + b0f;
                float v1 = acc[m][n][h*2+1] + b1f;
                ps0 += v0; ps1 += v1;
                *reinterpret_cast<float2*>(g_xc + t0*CC_ + co) = make_float2(v0, v1);
                *reinterpret_cast<__half2*>(g_xcs + (t0 << 7) + co) =
                    __floats2half2_rn(v0, v1);
            }
        }
        atomicAdd(&spool[co], ps0);
        atomicAdd(&spool[co + 1], ps1);
    }
    __syncthreads();
    if (tid < 128) atomicAdd(&g_pooled[b*CC_ + tid], spool[tid]);
}

// ---------------------------------------------------------------------------
// gate: 512 threads = 128 outputs x 4 K-quarters; also emits (g*dt_w) fp16.
__global__ __launch_bounds__(512) void gate_kernel(
    const float* __restrict__ g1w, const float* __restrict__ g1b,
    const float* __restrict__ g2w, const float* __restrict__ g2b,
    const float* __restrict__ dtw)
{
    const int b = blockIdx.x;
    const int tid = threadIdx.x;
    const int o = tid & 127;
    const int h = tid >> 7;
    __shared__ float sp[CC_], st[CC_], part[512], sgate[CC_];

    if (tid < 128) sp[tid] = g_pooled[b*CC_ + tid] * (1.f/(float)LL);
    __syncthreads();

    {
        const float4* wv = reinterpret_cast<const float4*>(g1w + o*CC_ + h*32);
        const float4* xv = reinterpret_cast<const float4*>(sp + h*32);
        float a0 = 0.f, a1 = 0.f;
#pragma unroll
        for (int i = 0; i < 8; i += 2) {
            float4 w0 = wv[i],   x0 = xv[i];
            float4 w1 = wv[i+1], x1 = xv[i+1];
            a0 = fmaf(w0.x,x0.x, fmaf(w0.y,x0.y, fmaf(w0.z,x0.z, fmaf(w0.w,x0.w, a0))));
            a1 = fmaf(w1.x,x1.x, fmaf(w1.y,x1.y, fmaf(w1.z,x1.z, fmaf(w1.w,x1.w, a1))));
        }
        part[tid] = a0 + a1;
    }
    __syncthreads();
    if (tid < 128)
        st[tid] = fmaxf(part[tid] + part[tid+128] + part[tid+256] + part[tid+384]
                        + g1b[tid], 0.f);
    __syncthreads();

    {
        const float4* wv = reinterpret_cast<const float4*>(g2w + o*CC_ + h*32);
        const float4* xv = reinterpret_cast<const float4*>(st + h*32);
        float a0 = 0.f, a1 = 0.f;
#pragma unroll
        for (int i = 0; i < 8; i += 2) {
            float4 w0 = wv[i],   x0 = xv[i];
            float4 w1 = wv[i+1], x1 = xv[i+1];
            a0 = fmaf(w0.x,x0.x, fmaf(w0.y,x0.y, fmaf(w0.z,x0.z, fmaf(w0.w,x0.w, a0))));
            a1 = fmaf(w1.x,x1.x, fmaf(w1.y,x1.y, fmaf(w1.z,x1.z, fmaf(w1.w,x1.w, a1))));
        }
        part[tid] = a0 + a1;
    }
    __syncthreads();
    if (tid < 128) {
        float z = part[tid] + part[tid+128] + part[tid+256] + part[tid+384] + g2b[tid];
        float g = 1.f / (1.f + __expf(-z));
        sgate[tid] = g;
        g_gate[b*CC_ + tid] = g;
    }
    __syncthreads();

    __half* gw = g_gw + (long)b*CC_*CC_;
#pragma unroll
    for (int i = 0; i < 16; i++) {
        int idx = tid + i*512;
        int oo = idx >> 6, cp = (idx & 63) * 2;
        float w0 = dtw[oo*CC_ + cp]     * sgate[cp];
        float w1 = dtw[oo*CC_ + cp + 1] * sgate[cp + 1];
        *reinterpret_cast<__half2*>(gw + oo*CC_ + cp) = __floats2half2_rn(w0, w1);
    }
}

// ---------------------------------------------------------------------------
// dt = sigmoid( xc @ (g*W)^T + b ) via HMMA fp16, single product.
// A and B both via cp.async (B from precomputed g_gw fp16).
#define RS2 272
#define DOFF_A 0
#define DOFF_B 34816

__global__ __launch_bounds__(256, 2) void dt_mma_kernel(const float* __restrict__ dtb)
{
    extern __shared__ char dyn2[];
    const uint32_t sb = smem_u32(dyn2);
    const int tid  = threadIdx.x;
    const int wid  = tid >> 5;
    const int lane = tid & 31;
    const int mw   = wid & 3;
    const int nw   = wid >> 2;
    const int m0   = blockIdx.x * 128;
    const int b    = m0 >> 12;

    const __half* gw = g_gw + (long)b*CC_*CC_;
#pragma unroll
    for (int i = 0; i < 16; i++) {
        int idx = tid + i*256;
        if (idx < 2048) {
            int tk = idx >> 4, k8 = idx & 15;
            cp16(sb + DOFF_A + tk*RS2 + k8*16, g_xcs + ((long)(m0 + tk) << 7) + (k8 << 3));
        } else {
            int j = idx - 2048;
            int o = j >> 4, k8 = j & 15;
            cp16(sb + DOFF_B + o*RS2 + k8*16, gw + o*CC_ + (k8 << 3));
        }
    }
    cp_commit();
    cp_wait<0>();
    __syncthreads();

    float acc[2][8][4];
#pragma unroll
    for (int m = 0; m < 2; m++)
#pragma unroll
        for (int n = 0; n < 8; n++)
#pragma unroll
            for (int j = 0; j < 4; j++) acc[m][n][j] = 0.f;

    const uint32_t lrow  = (lane & 15);
    const uint32_t lhalf = (lane >> 4) * 16;

    {
        const uint32_t a0 = sb + DOFF_A + (mw*32 + lrow)*RS2 + lhalf;
        const uint32_t a1 = a0 + 16*RS2;
        const uint32_t bbase = sb + DOFF_B + (nw*64 + lrow)*RS2 + lhalf;
#pragma unroll
        for (int ks = 0; ks < 8; ks++) {
            uint32_t af[2][4];
            ldsm_x4(af[0][0], af[0][1], af[0][2], af[0][3], a0 + ks*32);
            ldsm_x4(af[1][0], af[1][1], af[1][2], af[1][3], a1 + ks*32);
            uint32_t bf[8][2];
#pragma unroll
            for (int q = 0; q < 4; q++) {
                uint32_t r0, r1, r2, r3;
                ldsm_x4(r0, r1, r2, r3, bbase + q*16*RS2 + ks*32);
                bf[q*2][0] = r0;   bf[q*2][1] = r2;
                bf[q*2+1][0] = r1; bf[q*2+1][1] = r3;
            }
#pragma unroll
            for (int m = 0; m < 2; m++)
#pragma unroll
                for (int n = 0; n < 8; n++)
                    mma16816(acc[m][n], af[m][0], af[m][1], af[m][2], af[m][3],
                             bf[n][0], bf[n][1]);
        }
    }

    const int qrow = lane >> 2;
    const int qcol = (lane & 3) * 2;
    const long tokbase = (long)m0 + mw*32;
#pragma unroll
    for (int n = 0; n < 8; n++) {
        const int co = nw*64 + n*8 + qcol;
        const float b0 = dtb[co], b1 = dtb[co + 1];
#pragma unroll
        for (int m = 0; m < 2; m++) {
#pragma unroll
            for (int h = 0; h < 2; h++) {
                long t0 = tokbase + m*16 + qrow + h*8;
                float z0 = acc[m][n][h*2]   + b0;
                float z1 = acc[m][n][h*2+1] + b1;
                float2 v = make_float2(1.f/(1.f + __expf(-z0)), 1.f/(1.f + __expf(-z1)));
                *reinterpret_cast<float2*>(g_dt + t0*CC_ + co) = v;
            }
        }
    }
}

// ---------------------------------------------------------------------------
// SSM parallel scan, pass 1: per (b,c,seg) local scan from h=0. SEGLEN=64.
// 4-token register load batching for MLP.
__global__ __launch_bounds__(128) void scan_p1_kernel(const float* __restrict__ Araw)
{
    const int b   = blockIdx.x >> 6;
    const int seg = blockIdx.x & 63;
    const int c   = threadIdx.x;

    const float gc = g_gate[b*CC_ + c];
    float An2[SS], h[SS];
#pragma unroll
    for (int s = 0; s < SS; s++) {
        An2[s] = -__expf(Araw[c*SS + s]) * 1.4426950408889634f;
        h[s] = 0.f;
    }

    const float* xcp = g_xc + ((long)(b*LL) + seg*SEGLEN)*CC_ + c;
    const float* dtp = g_dt + ((long)(b*LL) + seg*SEGLEN)*CC_ + c;
    float sdt = 0.f;

    for (int t0 = 0; t0 < SEGLEN; t0 += 4) {
        float xv[4], dv[4];
#pragma unroll
        for (int j = 0; j < 4; j++) {
            xv[j] = xcp[(t0+j)*CC_];
            dv[j] = dtp[(t0+j)*CC_];
        }
#pragma unroll
        for (int j = 0; j < 4; j++) {
            float x = xv[j] * gc;
            sdt += dv[j];
#pragma unroll
            for (int s = 0; s < SS; s++)
                h[s] = fmaf(h[s], exp2f(An2[s]*dv[j]), x);
        }
    }
    const long pair = (long)b*CC_ + c;
    float* Cp = g_C + (pair*NSEG + seg)*SS;
#pragma unroll
    for (int s = 0; s < SS; s++) Cp[s] = h[s];
    g_Sdt[pair*NSEG + seg] = sdt;
}

// pass 2: per (b,c) serial scan over 64 segment summaries.
__global__ __launch_bounds__(256) void scan_fix_kernel(const float* __restrict__ Araw)
{
    const int pair = blockIdx.x*16 + (threadIdx.x >> 4);
    const int s    = threadIdx.x & 15;
    const int c    = pair & 127;
    const float An2 = -__expf(Araw[c*SS + s]) * 1.4426950408889634f;

    float h = 0.f;
    const float* Cp = g_C + (long)pair*NSEG*SS;
    const float* Sp = g_Sdt + (long)pair*NSEG;
    float* Hp = g_hin + (long)pair*NSEG*SS;
#pragma unroll 4
    for (int k = 0; k < NSEG; k++) {
        Hp[k*SS + s] = h;
        h = fmaf(h, exp2f(An2 * Sp[k]), Cp[k*SS + s]);
    }
}

// pass 3: rerun each segment from correct h_in, produce y, write NCHW + identity.
__global__ __launch_bounds__(128) void scan_p3_kernel(
    const float* __restrict__ x0,
    const float* __restrict__ Araw,
    const float* __restrict__ Draw,
    float* __restrict__ out)
{
    const int b   = blockIdx.x >> 6;
    const int seg = blockIdx.x & 63;
    const int c   = threadIdx.x;
    const int lane = c & 31;
    const int wrp  = c >> 5;

    __shared__ float ybuf[32][129];

    const float gc = g_gate[b*CC_ + c];
    const float Dp = __expf(Draw[c]);
    float An[SS], An2[SS], h[SS];
    const long pair = (long)b*CC_ + c;
    const float* Hp = g_hin + (pair*NSEG + seg)*SS;
#pragma unroll
    for (int s = 0; s < SS; s++) {
        An[s]  = -__expf(Araw[c*SS + s]);
        An2[s] = An[s] * 1.4426950408889634f;
        h[s]   = Hp[s];
    }

    const float* xcp = g_xc + ((long)(b*LL) + seg*SEGLEN)*CC_ + c;
    const float* dtp = g_dt + ((long)(b*LL) + seg*SEGLEN)*CC_ + c;
    const long l0 = (long)seg*SEGLEN;

    for (int ch = 0; ch < SEGLEN/32; ch++) {
        for (int tb = 0; tb < 32; tb += 4) {
            float xv[4], dv[4];
#pragma unroll
            for (int j = 0; j < 4; j++) {
                int tt = ch*32 + tb + j;
                xv[j] = xcp[tt*CC_];
                dv[j] = dtp[tt*CC_];
            }
#pragma unroll
            for (int j = 0; j < 4; j++) {
                float x = xv[j] * gc;
                float y = Dp * x;
#pragma unroll
                for (int s = 0; s < SS; s++) {
                    h[s] = fmaf(h[s], exp2f(An2[s]*dv[j]), x);
                    y = fmaf(h[s], An[s], y);
                }
                ybuf[tb + j][c] = y;
            }
        }
        __syncthreads();
#pragma unroll 4
        for (int cc = 0; cc < 32; cc++) {
            int co = wrp*32 + cc;
            long gidx = ((long)(b*CC_ + co) << 12) + l0 + ch*32 + lane;
            out[gidx] = ybuf[lane][co] + x0[gidx];
        }
        __syncthreads();
    }
}

// ---------------------------------------------------------------------------
extern "C" void kernel_launch(void* const* d_in, const int* in_sizes, int n_in,
                              void* d_out, int out_size)
{
    const float* x      = (const float*)d_in[0];
    const float* conv_w = (const float*)d_in[1];
    const float* conv_b = (const float*)d_in[2];
    const float* dt_w   = (const float*)d_in[3];
    const float* dt_b   = (const float*)d_in[4];
    const float* A      = (const float*)d_in[5];
    const float* D      = (const float*)d_in[6];
    const float* g1_w   = (const float*)d_in[7];
    const float* g1_b   = (const float*)d_in[8];
    const float* g2_w   = (const float*)d_in[9];
    const float* g2_b   = (const float*)d_in[10];
    float* out = (float*)d_out;

    const int conv_smem = 2 * BUFB;        // 73728
    const int dt_smem   = 2 * 34816;       // 69632
    cudaFuncSetAttribute(conv_mma_kernel, cudaFuncAttributeMaxDynamicSharedMemorySize, conv_smem);
    cudaFuncSetAttribute(dt_mma_kernel,   cudaFuncAttributeMaxDynamicSharedMemorySize, dt_smem);

    const int prep_blocks = 66*BB + (9*128*128 + 255)/256;
    prep_kernel<<<prep_blocks, 256>>>(x, conv_w);
    conv_mma_kernel<<<BB*32, 256, conv_smem>>>(conv_b);
    gate_kernel<<<BB, 512>>>(g1_w, g1_b, g2_w, g2_b, dt_w);
    dt_mma_kernel<<<(BB*LL)/128, 256, dt_smem>>>(dt_b);
    scan_p1_kernel<<<BB*NSEG, 128>>>(A);
    scan_fix_kernel<<<BB*CC_/16, 256>>>(A);
    scan_p3_kernel<<<BB*NSEG, 128>>>(x, A, D, out);
}